// round 1
// baseline (speedup 1.0000x reference)
#include <cuda_runtime.h>
#include <math.h>

// Problem constants
#define B_    8
#define NQ_   1024
#define DV_   512
#define H_    8
#define DS_   64
#define MROWS (B_ * NQ_)   // 8192

// ---------------- scratch (no allocation allowed) ----------------
__device__ float g_Qp[MROWS * DV_];
__device__ float g_Kp[MROWS * DV_];
__device__ float g_Vp[MROWS * DV_];
__device__ float g_Oh[MROWS * DV_];
__device__ float g_X1[MROWS * DV_];
__device__ float g_Y [MROWS * DV_];

// =================================================================
// SGEMM: C[M,512] = A[M,512] @ W[512,512] + bias  (optionally
// epilogue: C = A + relu(C))   BM=BN=128, BK=8, 256 threads, 8x8 micro
// =================================================================
__global__ __launch_bounds__(256) void sgemm512(
    const float* __restrict__ A, const float* __restrict__ W,
    const float* __restrict__ bias, float* __restrict__ C,
    int do_epi)
{
    __shared__ float As[8][128];
    __shared__ float Bs[8][128];

    const int tid = threadIdx.x;
    const int tx  = tid & 15;        // 0..15 -> n micro tile
    const int ty  = tid >> 4;        // 0..15 -> m micro tile
    const int m0  = blockIdx.y * 128;
    const int n0  = blockIdx.x * 128;

    const int ar = tid >> 1;         // 0..127
    const int ac = (tid & 1) * 4;    // 0 or 4
    const int wr = tid >> 5;         // 0..7
    const int wc = (tid & 31) * 4;   // 0..124

    float acc[8][8];
#pragma unroll
    for (int i = 0; i < 8; i++)
#pragma unroll
        for (int j = 0; j < 8; j++) acc[i][j] = 0.f;

    for (int k0 = 0; k0 < 512; k0 += 8) {
        float4 av = *(const float4*)&A[(size_t)(m0 + ar) * 512 + k0 + ac];
        float4 wv = *(const float4*)&W[(size_t)(k0 + wr) * 512 + n0 + wc];
        __syncthreads();
        As[ac + 0][ar] = av.x;
        As[ac + 1][ar] = av.y;
        As[ac + 2][ar] = av.z;
        As[ac + 3][ar] = av.w;
        *(float4*)&Bs[wr][wc] = wv;
        __syncthreads();
#pragma unroll
        for (int kk = 0; kk < 8; kk++) {
            float a[8], b[8];
            *(float4*)(a)     = *(const float4*)&As[kk][ty * 8];
            *(float4*)(a + 4) = *(const float4*)&As[kk][ty * 8 + 4];
            *(float4*)(b)     = *(const float4*)&Bs[kk][tx * 8];
            *(float4*)(b + 4) = *(const float4*)&Bs[kk][tx * 8 + 4];
#pragma unroll
            for (int i = 0; i < 8; i++)
#pragma unroll
                for (int j = 0; j < 8; j++) acc[i][j] += a[i] * b[j];
        }
    }

#pragma unroll
    for (int i = 0; i < 8; i++) {
        const int m = m0 + ty * 8 + i;
#pragma unroll
        for (int j = 0; j < 8; j++) {
            const int n = n0 + tx * 8 + j;
            float c = acc[i][j] + bias[n];
            if (do_epi) c = A[(size_t)m * 512 + n] + fmaxf(c, 0.f);
            C[(size_t)m * 512 + n] = c;
        }
    }
}

// =================================================================
// Attention: one CTA per (b, h, 64-query block). Flash-style online
// softmax over 16 K-tiles of 64. Output = Qh + softmax(QK^T/s) V.
// =================================================================
#define AP 68   // smem pitch (floats), 16B-aligned

__global__ __launch_bounds__(256) void attn512(
    const float* __restrict__ Qp, const float* __restrict__ Kp,
    const float* __restrict__ Vp, float* __restrict__ Oh)
{
    extern __shared__ float sm[];
    float* Qt = sm;                // [s][q] transposed, 64 x AP
    float* Kt = sm + 64 * AP;      // [s][k] transposed
    float* Vs = sm + 2 * 64 * AP;  // [k][s]
    float* Ps = sm + 3 * 64 * AP;  // [k][q] transposed P

    const int tid = threadIdx.x;
    const int tx  = tid & 15;
    const int ty  = tid >> 4;
    const int qb  = blockIdx.x;
    const int h   = blockIdx.y;
    const int b   = blockIdx.z;

    const float* Qbase = Qp + ((size_t)(b * NQ_ + qb * 64)) * DV_ + h * DS_;

    for (int idx = tid; idx < 64 * 64; idx += 256) {
        const int q = idx >> 6, s = idx & 63;
        Qt[s * AP + q] = Qbase[(size_t)q * DV_ + s];
    }

    float m_i[4], l_i[4], acc[4][4];
#pragma unroll
    for (int i = 0; i < 4; i++) {
        m_i[i] = -1e30f; l_i[i] = 0.f;
#pragma unroll
        for (int j = 0; j < 4; j++) acc[i][j] = 0.f;
    }
    const float scale = 0.04419417382415922f;  // 1/sqrt(512)

    for (int kb = 0; kb < 16; kb++) {
        __syncthreads();   // protect Kt/Vs/Ps from previous iteration readers
        const float* Kbase = Kp + ((size_t)(b * NQ_ + kb * 64)) * DV_ + h * DS_;
        const float* Vbase = Vp + ((size_t)(b * NQ_ + kb * 64)) * DV_ + h * DS_;
        for (int idx = tid; idx < 64 * 64; idx += 256) {
            const int k = idx >> 6, s = idx & 63;
            Kt[s * AP + k] = Kbase[(size_t)k * DV_ + s];
            Vs[k * AP + s] = Vbase[(size_t)k * DV_ + s];
        }
        __syncthreads();

        // S = Q K^T for this tile: thread owns rows ty*4..+3, cols tx*4..+3
        float S[4][4];
#pragma unroll
        for (int i = 0; i < 4; i++)
#pragma unroll
            for (int j = 0; j < 4; j++) S[i][j] = 0.f;

        for (int s = 0; s < 64; s++) {
            float4 qv = *(const float4*)&Qt[s * AP + ty * 4];
            float4 kv = *(const float4*)&Kt[s * AP + tx * 4];
            float qa[4] = {qv.x, qv.y, qv.z, qv.w};
            float ka[4] = {kv.x, kv.y, kv.z, kv.w};
#pragma unroll
            for (int i = 0; i < 4; i++)
#pragma unroll
                for (int j = 0; j < 4; j++) S[i][j] += qa[i] * ka[j];
        }

        // online softmax (rows distributed over 16 lanes with same ty)
#pragma unroll
        for (int i = 0; i < 4; i++) {
#pragma unroll
            for (int j = 0; j < 4; j++) S[i][j] *= scale;
            float mx = fmaxf(fmaxf(S[i][0], S[i][1]), fmaxf(S[i][2], S[i][3]));
#pragma unroll
            for (int off = 8; off; off >>= 1)
                mx = fmaxf(mx, __shfl_xor_sync(0xffffffffu, mx, off));
            const float mnew  = fmaxf(m_i[i], mx);
            const float alpha = __expf(m_i[i] - mnew);
            m_i[i] = mnew;
            float rs = 0.f;
#pragma unroll
            for (int j = 0; j < 4; j++) {
                const float p = __expf(S[i][j] - mnew);
                S[i][j] = p;
                rs += p;
            }
#pragma unroll
            for (int off = 8; off; off >>= 1)
                rs += __shfl_xor_sync(0xffffffffu, rs, off);
            l_i[i] = l_i[i] * alpha + rs;
#pragma unroll
            for (int j = 0; j < 4; j++) acc[i][j] *= alpha;
        }

        // write P transposed [k][q]
#pragma unroll
        for (int i = 0; i < 4; i++)
#pragma unroll
            for (int j = 0; j < 4; j++)
                Ps[(tx * 4 + j) * AP + ty * 4 + i] = S[i][j];
        __syncthreads();

        // O += P V
        for (int k = 0; k < 64; k++) {
            float4 pv = *(const float4*)&Ps[k * AP + ty * 4];
            float4 vv = *(const float4*)&Vs[k * AP + tx * 4];
            float pa[4] = {pv.x, pv.y, pv.z, pv.w};
            float va[4] = {vv.x, vv.y, vv.z, vv.w};
#pragma unroll
            for (int i = 0; i < 4; i++)
#pragma unroll
                for (int j = 0; j < 4; j++) acc[i][j] += pa[i] * va[j];
        }
    }

    float* Obase = Oh + ((size_t)(b * NQ_ + qb * 64)) * DV_ + h * DS_;
#pragma unroll
    for (int i = 0; i < 4; i++) {
        const float inv = 1.f / l_i[i];
        const int q = ty * 4 + i;
#pragma unroll
        for (int j = 0; j < 4; j++) {
            const int s = tx * 4 + j;
            Obase[(size_t)q * DV_ + s] = Qt[s * AP + q] + acc[i][j] * inv;
        }
    }
}

// =================================================================
// LayerNorm over last dim (512), one row per block, 256 threads
// =================================================================
__global__ __launch_bounds__(256) void layernorm512(
    const float* __restrict__ X, const float* __restrict__ g,
    const float* __restrict__ bb, float* __restrict__ Y)
{
    const int row = blockIdx.x;
    const int tid = threadIdx.x;
    const float* x = X + (size_t)row * 512;

    const float v0 = x[tid];
    const float v1 = x[tid + 256];
    float s  = v0 + v1;
    float sq = v0 * v0 + v1 * v1;

    __shared__ float red[16];
#pragma unroll
    for (int off = 16; off; off >>= 1) {
        s  += __shfl_xor_sync(0xffffffffu, s,  off);
        sq += __shfl_xor_sync(0xffffffffu, sq, off);
    }
    const int wid = tid >> 5, lane = tid & 31;
    if (lane == 0) { red[wid * 2] = s; red[wid * 2 + 1] = sq; }
    __syncthreads();
    float sum = 0.f, sumsq = 0.f;
#pragma unroll
    for (int w = 0; w < 8; w++) { sum += red[w * 2]; sumsq += red[w * 2 + 1]; }
    const float mean = sum * (1.f / 512.f);
    const float var  = sumsq * (1.f / 512.f) - mean * mean;
    const float r    = rsqrtf(var + 1e-5f);

    Y[(size_t)row * 512 + tid]       = (v0 - mean) * r * g[tid]       + bb[tid];
    Y[(size_t)row * 512 + tid + 256] = (v1 - mean) * r * g[tid + 256] + bb[tid + 256];
}

// =================================================================
// Host launcher
// =================================================================
extern "C" void kernel_launch(void* const* d_in, const int* in_sizes, int n_in,
                              void* d_out, int out_size)
{
    const float* Q  = (const float*)d_in[0];
    const float* K  = (const float*)d_in[1];
    const float* Wq = (const float*)d_in[2];
    const float* bq = (const float*)d_in[3];
    const float* Wk = (const float*)d_in[4];
    const float* bk = (const float*)d_in[5];
    const float* Wv = (const float*)d_in[6];
    const float* bv = (const float*)d_in[7];
    const float* Wo = (const float*)d_in[8];
    const float* bo = (const float*)d_in[9];
    const float* g0 = (const float*)d_in[10];
    const float* b0 = (const float*)d_in[11];
    const float* g1 = (const float*)d_in[12];
    const float* b1 = (const float*)d_in[13];
    float* out = (float*)d_out;

    float *pQp, *pKp, *pVp, *pOh, *pX1, *pY;
    cudaGetSymbolAddress((void**)&pQp, g_Qp);
    cudaGetSymbolAddress((void**)&pKp, g_Kp);
    cudaGetSymbolAddress((void**)&pVp, g_Vp);
    cudaGetSymbolAddress((void**)&pOh, g_Oh);
    cudaGetSymbolAddress((void**)&pX1, g_X1);
    cudaGetSymbolAddress((void**)&pY,  g_Y);

    const int smem_attn = 4 * 64 * AP * sizeof(float);  // 69632 B
    cudaFuncSetAttribute(attn512, cudaFuncAttributeMaxDynamicSharedMemorySize,
                         smem_attn);

    dim3 ggrid(512 / 128, MROWS / 128);   // (4, 64)

    // 1) projections
    sgemm512<<<ggrid, 256>>>(Q, Wq, bq, pQp, 0);
    sgemm512<<<ggrid, 256>>>(K, Wk, bk, pKp, 0);
    sgemm512<<<ggrid, 256>>>(K, Wv, bv, pVp, 0);

    // 2) attention + Q residual
    dim3 agrid(NQ_ / 64, H_, B_);
    attn512<<<agrid, 256, smem_attn>>>(pQp, pKp, pVp, pOh);

    // 3) LN0
    layernorm512<<<MROWS, 256>>>(pOh, g0, b0, pX1);

    // 4) MLP: Y = X1 + relu(X1 @ Wo + bo)
    sgemm512<<<ggrid, 256>>>(pX1, Wo, bo, pY, 1);

    // 5) LN1 -> out
    layernorm512<<<MROWS, 256>>>(pY, g1, b1, out);
}

// round 2
// speedup vs baseline: 1.0032x; 1.0032x over previous
#include <cuda_runtime.h>
#include <math.h>

// Problem constants
#define B_    8
#define NQ_   1024
#define DV_   512
#define H_    8
#define DS_   64
#define MROWS (B_ * NQ_)   // 8192

// ---------------- scratch (no allocation allowed) ----------------
__device__ float g_Qp[MROWS * DV_];
__device__ float g_Kp[MROWS * DV_];
__device__ float g_Vp[MROWS * DV_];
__device__ float g_Oh[MROWS * DV_];
__device__ float g_X1[MROWS * DV_];
__device__ float g_Y [MROWS * DV_];

// =================================================================
// SGEMM: C[M,512] = A[M,512] @ W[512,512] + bias  (optionally
// epilogue: C = A + relu(C))   BM=BN=128, BK=8, 256 threads, 8x8 micro
// =================================================================
__global__ __launch_bounds__(256) void sgemm512(
    const float* __restrict__ A, const float* __restrict__ W,
    const float* __restrict__ bias, float* __restrict__ C,
    int do_epi)
{
    __shared__ float As[8][128];
    __shared__ float Bs[8][128];

    const int tid = threadIdx.x;
    const int tx  = tid & 15;        // 0..15 -> n micro tile
    const int ty  = tid >> 4;        // 0..15 -> m micro tile
    const int m0  = blockIdx.y * 128;
    const int n0  = blockIdx.x * 128;

    const int ar = tid >> 1;         // 0..127
    const int ac = (tid & 1) * 4;    // 0 or 4
    const int wr = tid >> 5;         // 0..7
    const int wc = (tid & 31) * 4;   // 0..124

    float acc[8][8];
#pragma unroll
    for (int i = 0; i < 8; i++)
#pragma unroll
        for (int j = 0; j < 8; j++) acc[i][j] = 0.f;

    for (int k0 = 0; k0 < 512; k0 += 8) {
        float4 av = *(const float4*)&A[(size_t)(m0 + ar) * 512 + k0 + ac];
        float4 wv = *(const float4*)&W[(size_t)(k0 + wr) * 512 + n0 + wc];
        __syncthreads();
        As[ac + 0][ar] = av.x;
        As[ac + 1][ar] = av.y;
        As[ac + 2][ar] = av.z;
        As[ac + 3][ar] = av.w;
        *(float4*)&Bs[wr][wc] = wv;
        __syncthreads();
#pragma unroll
        for (int kk = 0; kk < 8; kk++) {
            float a[8], b[8];
            *(float4*)(a)     = *(const float4*)&As[kk][ty * 8];
            *(float4*)(a + 4) = *(const float4*)&As[kk][ty * 8 + 4];
            *(float4*)(b)     = *(const float4*)&Bs[kk][tx * 8];
            *(float4*)(b + 4) = *(const float4*)&Bs[kk][tx * 8 + 4];
#pragma unroll
            for (int i = 0; i < 8; i++)
#pragma unroll
                for (int j = 0; j < 8; j++) acc[i][j] += a[i] * b[j];
        }
    }

#pragma unroll
    for (int i = 0; i < 8; i++) {
        const int m = m0 + ty * 8 + i;
#pragma unroll
        for (int j = 0; j < 8; j++) {
            const int n = n0 + tx * 8 + j;
            float c = acc[i][j] + bias[n];
            if (do_epi) c = A[(size_t)m * 512 + n] + fmaxf(c, 0.f);
            C[(size_t)m * 512 + n] = c;
        }
    }
}

// =================================================================
// Attention: one CTA per (b, h, 64-query block). Flash-style online
// softmax over 16 K-tiles of 64. Output = Qh + softmax(QK^T/s) V.
// =================================================================
#define AP 68   // smem pitch (floats), 16B-aligned

__global__ __launch_bounds__(256) void attn512(
    const float* __restrict__ Qp, const float* __restrict__ Kp,
    const float* __restrict__ Vp, float* __restrict__ Oh)
{
    extern __shared__ float sm[];
    float* Qt = sm;                // [s][q] transposed, 64 x AP
    float* Kt = sm + 64 * AP;      // [s][k] transposed
    float* Vs = sm + 2 * 64 * AP;  // [k][s]
    float* Ps = sm + 3 * 64 * AP;  // [k][q] transposed P

    const int tid = threadIdx.x;
    const int tx  = tid & 15;
    const int ty  = tid >> 4;
    const int qb  = blockIdx.x;
    const int h   = blockIdx.y;
    const int b   = blockIdx.z;

    const float* Qbase = Qp + ((size_t)(b * NQ_ + qb * 64)) * DV_ + h * DS_;

    for (int idx = tid; idx < 64 * 64; idx += 256) {
        const int q = idx >> 6, s = idx & 63;
        Qt[s * AP + q] = Qbase[(size_t)q * DV_ + s];
    }

    float m_i[4], l_i[4], acc[4][4];
#pragma unroll
    for (int i = 0; i < 4; i++) {
        m_i[i] = -1e30f; l_i[i] = 0.f;
#pragma unroll
        for (int j = 0; j < 4; j++) acc[i][j] = 0.f;
    }
    const float scale = 0.04419417382415922f;  // 1/sqrt(512)

    for (int kb = 0; kb < 16; kb++) {
        __syncthreads();   // protect Kt/Vs/Ps from previous iteration readers
        const float* Kbase = Kp + ((size_t)(b * NQ_ + kb * 64)) * DV_ + h * DS_;
        const float* Vbase = Vp + ((size_t)(b * NQ_ + kb * 64)) * DV_ + h * DS_;
        for (int idx = tid; idx < 64 * 64; idx += 256) {
            const int k = idx >> 6, s = idx & 63;
            Kt[s * AP + k] = Kbase[(size_t)k * DV_ + s];
            Vs[k * AP + s] = Vbase[(size_t)k * DV_ + s];
        }
        __syncthreads();

        // S = Q K^T for this tile: thread owns rows ty*4..+3, cols tx*4..+3
        float S[4][4];
#pragma unroll
        for (int i = 0; i < 4; i++)
#pragma unroll
            for (int j = 0; j < 4; j++) S[i][j] = 0.f;

        for (int s = 0; s < 64; s++) {
            float4 qv = *(const float4*)&Qt[s * AP + ty * 4];
            float4 kv = *(const float4*)&Kt[s * AP + tx * 4];
            float qa[4] = {qv.x, qv.y, qv.z, qv.w};
            float ka[4] = {kv.x, kv.y, kv.z, kv.w};
#pragma unroll
            for (int i = 0; i < 4; i++)
#pragma unroll
                for (int j = 0; j < 4; j++) S[i][j] += qa[i] * ka[j];
        }

        // online softmax (rows distributed over 16 lanes with same ty)
#pragma unroll
        for (int i = 0; i < 4; i++) {
#pragma unroll
            for (int j = 0; j < 4; j++) S[i][j] *= scale;
            float mx = fmaxf(fmaxf(S[i][0], S[i][1]), fmaxf(S[i][2], S[i][3]));
#pragma unroll
            for (int off = 8; off; off >>= 1)
                mx = fmaxf(mx, __shfl_xor_sync(0xffffffffu, mx, off));
            const float mnew  = fmaxf(m_i[i], mx);
            const float alpha = __expf(m_i[i] - mnew);
            m_i[i] = mnew;
            float rs = 0.f;
#pragma unroll
            for (int j = 0; j < 4; j++) {
                const float p = __expf(S[i][j] - mnew);
                S[i][j] = p;
                rs += p;
            }
#pragma unroll
            for (int off = 8; off; off >>= 1)
                rs += __shfl_xor_sync(0xffffffffu, rs, off);
            l_i[i] = l_i[i] * alpha + rs;
#pragma unroll
            for (int j = 0; j < 4; j++) acc[i][j] *= alpha;
        }

        // write P transposed [k][q]
#pragma unroll
        for (int i = 0; i < 4; i++)
#pragma unroll
            for (int j = 0; j < 4; j++)
                Ps[(tx * 4 + j) * AP + ty * 4 + i] = S[i][j];
        __syncthreads();

        // O += P V
        for (int k = 0; k < 64; k++) {
            float4 pv = *(const float4*)&Ps[k * AP + ty * 4];
            float4 vv = *(const float4*)&Vs[k * AP + tx * 4];
            float pa[4] = {pv.x, pv.y, pv.z, pv.w};
            float va[4] = {vv.x, vv.y, vv.z, vv.w};
#pragma unroll
            for (int i = 0; i < 4; i++)
#pragma unroll
                for (int j = 0; j < 4; j++) acc[i][j] += pa[i] * va[j];
        }
    }

    float* Obase = Oh + ((size_t)(b * NQ_ + qb * 64)) * DV_ + h * DS_;
#pragma unroll
    for (int i = 0; i < 4; i++) {
        const float inv = 1.f / l_i[i];
        const int q = ty * 4 + i;
#pragma unroll
        for (int j = 0; j < 4; j++) {
            const int s = tx * 4 + j;
            Obase[(size_t)q * DV_ + s] = Qt[s * AP + q] + acc[i][j] * inv;
        }
    }
}

// =================================================================
// LayerNorm over last dim (512), one row per block, 256 threads
// =================================================================
__global__ __launch_bounds__(256) void layernorm512(
    const float* __restrict__ X, const float* __restrict__ g,
    const float* __restrict__ bb, float* __restrict__ Y)
{
    const int row = blockIdx.x;
    const int tid = threadIdx.x;
    const float* x = X + (size_t)row * 512;

    const float v0 = x[tid];
    const float v1 = x[tid + 256];
    float s  = v0 + v1;
    float sq = v0 * v0 + v1 * v1;

    __shared__ float red[16];
#pragma unroll
    for (int off = 16; off; off >>= 1) {
        s  += __shfl_xor_sync(0xffffffffu, s,  off);
        sq += __shfl_xor_sync(0xffffffffu, sq, off);
    }
    const int wid = tid >> 5, lane = tid & 31;
    if (lane == 0) { red[wid * 2] = s; red[wid * 2 + 1] = sq; }
    __syncthreads();
    float sum = 0.f, sumsq = 0.f;
#pragma unroll
    for (int w = 0; w < 8; w++) { sum += red[w * 2]; sumsq += red[w * 2 + 1]; }
    const float mean = sum * (1.f / 512.f);
    const float var  = sumsq * (1.f / 512.f) - mean * mean;
    const float r    = rsqrtf(var + 1e-5f);

    Y[(size_t)row * 512 + tid]       = (v0 - mean) * r * g[tid]       + bb[tid];
    Y[(size_t)row * 512 + tid + 256] = (v1 - mean) * r * g[tid + 256] + bb[tid + 256];
}

// =================================================================
// Host launcher
// =================================================================
extern "C" void kernel_launch(void* const* d_in, const int* in_sizes, int n_in,
                              void* d_out, int out_size)
{
    const float* Q  = (const float*)d_in[0];
    const float* K  = (const float*)d_in[1];
    const float* Wq = (const float*)d_in[2];
    const float* bq = (const float*)d_in[3];
    const float* Wk = (const float*)d_in[4];
    const float* bk = (const float*)d_in[5];
    const float* Wv = (const float*)d_in[6];
    const float* bv = (const float*)d_in[7];
    const float* Wo = (const float*)d_in[8];
    const float* bo = (const float*)d_in[9];
    const float* g0 = (const float*)d_in[10];
    const float* b0 = (const float*)d_in[11];
    const float* g1 = (const float*)d_in[12];
    const float* b1 = (const float*)d_in[13];
    float* out = (float*)d_out;

    float *pQp, *pKp, *pVp, *pOh, *pX1, *pY;
    cudaGetSymbolAddress((void**)&pQp, g_Qp);
    cudaGetSymbolAddress((void**)&pKp, g_Kp);
    cudaGetSymbolAddress((void**)&pVp, g_Vp);
    cudaGetSymbolAddress((void**)&pOh, g_Oh);
    cudaGetSymbolAddress((void**)&pX1, g_X1);
    cudaGetSymbolAddress((void**)&pY,  g_Y);

    const int smem_attn = 4 * 64 * AP * sizeof(float);  // 69632 B
    cudaFuncSetAttribute(attn512, cudaFuncAttributeMaxDynamicSharedMemorySize,
                         smem_attn);

    dim3 ggrid(512 / 128, MROWS / 128);   // (4, 64)

    // 1) projections
    sgemm512<<<ggrid, 256>>>(Q, Wq, bq, pQp, 0);
    sgemm512<<<ggrid, 256>>>(K, Wk, bk, pKp, 0);
    sgemm512<<<ggrid, 256>>>(K, Wv, bv, pVp, 0);

    // 2) attention + Q residual
    dim3 agrid(NQ_ / 64, H_, B_);
    attn512<<<agrid, 256, smem_attn>>>(pQp, pKp, pVp, pOh);

    // 3) LN0
    layernorm512<<<MROWS, 256>>>(pOh, g0, b0, pX1);

    // 4) MLP: Y = X1 + relu(X1 @ Wo + bo)
    sgemm512<<<ggrid, 256>>>(pX1, Wo, bo, pY, 1);

    // 5) LN1 -> out
    layernorm512<<<MROWS, 256>>>(pY, g1, b1, out);
}

// round 6
// speedup vs baseline: 2.6953x; 2.6868x over previous
#include <cuda_runtime.h>
#include <cuda_bf16.h>
#include <math.h>

typedef __nv_bfloat16 bf16;

#define B_    8
#define NQ_   1024
#define DV_   512
#define MROWS (B_ * NQ_)
#define BH_   64
#define SSTRIDE 40

__device__ bf16  g_Qhi[MROWS * DV_];
__device__ bf16  g_Qlo[MROWS * DV_];
__device__ bf16  g_Khi[MROWS * DV_];
__device__ bf16  g_Wqt_hi[DV_ * DV_];
__device__ bf16  g_Wqt_lo[DV_ * DV_];
__device__ bf16  g_Wkt[DV_ * DV_];
__device__ bf16  g_Wvt[DV_ * DV_];
__device__ bf16  g_Wot_hi[DV_ * DV_];
__device__ bf16  g_Wot_lo[DV_ * DV_];
__device__ float g_Qp [MROWS * DV_];
__device__ bf16  g_Qpb[MROWS * DV_];
__device__ bf16  g_Kpb[MROWS * DV_];
__device__ bf16  g_Vpb[MROWS * DV_];
__device__ bf16  g_Vt [BH_ * 64 * NQ_];
__device__ bf16  g_S  [(size_t)BH_ * NQ_ * NQ_];
__device__ float g_Oh [MROWS * DV_];
__device__ float g_X1 [MROWS * DV_];
__device__ bf16  g_X1hi[MROWS * DV_];
__device__ bf16  g_X1lo[MROWS * DV_];
__device__ float g_Y  [MROWS * DV_];

__device__ __forceinline__ unsigned smem_u32(const void* p) {
    unsigned a;
    asm("{ .reg .u64 t; cvta.to.shared.u64 t, %1; cvt.u32.u64 %0, t; }" : "=r"(a) : "l"(p));
    return a;
}
__device__ __forceinline__ unsigned pack2bf(float a, float b) {
    __nv_bfloat162 t = __floats2bfloat162_rn(a, b);
    return *reinterpret_cast<unsigned*>(&t);
}

#define LDSM_X4(R0, R1, R2, R3, ADDR) \
    asm volatile("ldmatrix.sync.aligned.m8n8.x4.shared.b16 {%0,%1,%2,%3}, [%4];" \
                 : "=r"(R0), "=r"(R1), "=r"(R2), "=r"(R3) : "r"(ADDR))

#define MMA16816(D, A, Bb) \
    asm volatile("mma.sync.aligned.m16n8k16.row.col.f32.bf16.bf16.f32 " \
                 "{%0,%1,%2,%3}, {%4,%5,%6,%7}, {%8,%9}, {%0,%1,%2,%3};" \
                 : "+f"((D)[0]), "+f"((D)[1]), "+f"((D)[2]), "+f"((D)[3]) \
                 : "r"((A)[0]), "r"((A)[1]), "r"((A)[2]), "r"((A)[3]), \
                   "r"((Bb)[0]), "r"((Bb)[1]))

// Block tile 128 x BN, 8 warps (4m x 2n), K chunks of 32.
// A[M,K] row-major lda, B[N,K] row-major ldb. acc accumulates.
template<int BN>
__device__ __forceinline__ void mainloop(
    const bf16* __restrict__ A, int lda,
    const bf16* __restrict__ B, int ldb, int K,
    bf16* As, bf16* Bs, float (*acc)[4])
{
    const int tid  = threadIdx.x;
    const int l    = tid & 31;
    const int warp = tid >> 5;
    const int wm   = warp & 3, wn = warp >> 2;
    const unsigned sAu = smem_u32(As), sBu = smem_u32(Bs);

    const int ar0 = tid >> 2,          ac0 = tid & 3;
    const int ar1 = (tid + 256) >> 2,  ac1 = tid & 3;
    const int br0 = tid >> 2,          bc0 = tid & 3;
    const int br1 = (tid + 256) >> 2,  bc1 = tid & 3;

    unsigned aAddr[2];
#pragma unroll
    for (int mt = 0; mt < 2; mt++)
        aAddr[mt] = sAu + (unsigned)(((wm * 32 + mt * 16 + (l & 15)) * SSTRIDE
                                      + (l >> 4) * 8) * 2);
    const int g = l >> 3, l8 = l & 7;
    unsigned bAddr[BN / 32];
#pragma unroll
    for (int j = 0; j < BN / 32; j++) {
        int row = wn * (BN / 2) + j * 16 + (g >> 1) * 8 + l8;
        bAddr[j] = sBu + (unsigned)((row * SSTRIDE + (g & 1) * 8) * 2);
    }

    uint4 pa0, pa1, pb0, pb1;
    pa0 = *(const uint4*)(A + (size_t)ar0 * lda + ac0 * 8);
    pa1 = *(const uint4*)(A + (size_t)ar1 * lda + ac1 * 8);
    pb0 = *(const uint4*)(B + (size_t)br0 * ldb + bc0 * 8);
    if (BN == 128) pb1 = *(const uint4*)(B + (size_t)br1 * ldb + bc1 * 8);

    const int nch = K >> 5;
    for (int kc = 0; kc < nch; kc++) {
        __syncthreads();
        *(uint4*)(As + ar0 * SSTRIDE + ac0 * 8) = pa0;
        *(uint4*)(As + ar1 * SSTRIDE + ac1 * 8) = pa1;
        *(uint4*)(Bs + br0 * SSTRIDE + bc0 * 8) = pb0;
        if (BN == 128) *(uint4*)(Bs + br1 * SSTRIDE + bc1 * 8) = pb1;
        __syncthreads();
        if (kc + 1 < nch) {
            const int ko = (kc + 1) * 32;
            pa0 = *(const uint4*)(A + (size_t)ar0 * lda + ko + ac0 * 8);
            pa1 = *(const uint4*)(A + (size_t)ar1 * lda + ko + ac1 * 8);
            pb0 = *(const uint4*)(B + (size_t)br0 * ldb + ko + bc0 * 8);
            if (BN == 128) pb1 = *(const uint4*)(B + (size_t)br1 * ldb + ko + bc1 * 8);
        }
#pragma unroll
        for (int s = 0; s < 2; s++) {
            unsigned af[2][4];
            LDSM_X4(af[0][0], af[0][1], af[0][2], af[0][3], aAddr[0] + s * 32);
            LDSM_X4(af[1][0], af[1][1], af[1][2], af[1][3], aAddr[1] + s * 32);
            unsigned bfm[BN / 16][2];
#pragma unroll
            for (int j = 0; j < BN / 32; j++)
                LDSM_X4(bfm[2 * j][0], bfm[2 * j][1],
                        bfm[2 * j + 1][0], bfm[2 * j + 1][1], bAddr[j] + s * 32);
#pragma unroll
            for (int mt = 0; mt < 2; mt++)
#pragma unroll
                for (int nt = 0; nt < BN / 16; nt++)
                    MMA16816(acc[mt * (BN / 16) + nt], af[mt], bfm[nt]);
        }
    }
}

// epi: 0 = bias -> f32 + bf16 ; 1 = bias -> bf16 ; 2 = Xres + relu -> f32
__global__ __launch_bounds__(256) void gemm_proj(
    const bf16* __restrict__ Ahi, const bf16* __restrict__ Alo,
    const bf16* __restrict__ Bhi, const bf16* __restrict__ Blo,
    const float* __restrict__ bias, const float* __restrict__ Xres,
    float* __restrict__ outF, bf16* __restrict__ outB, int npass, int epi)
{
    __shared__ bf16 As[128 * SSTRIDE], Bs[128 * SSTRIDE];
    float acc[16][4];
#pragma unroll
    for (int i = 0; i < 16; i++)
#pragma unroll
        for (int j = 0; j < 4; j++) acc[i][j] = 0.f;

    const int m0 = blockIdx.y * 128, n0 = blockIdx.x * 128;
    for (int p = 0; p < npass; p++) {
        const bf16* Ag = (p == 2) ? Alo : Ahi;
        const bf16* Bg = (p == 1) ? Blo : Bhi;
        mainloop<128>(Ag + (size_t)m0 * 512, 512, Bg + (size_t)n0 * 512, 512, 512,
                      As, Bs, acc);
    }

    const int tid = threadIdx.x, l = tid & 31, warp = tid >> 5;
    const int wm = warp & 3, wn = warp >> 2;
#pragma unroll
    for (int mt = 0; mt < 2; mt++)
#pragma unroll
        for (int nt = 0; nt < 8; nt++) {
            const float* c = acc[mt * 8 + nt];
            const int m = m0 + wm * 32 + mt * 16 + (l >> 2);
            const int n = n0 + wn * 64 + nt * 8 + (l & 3) * 2;
            const float bb0 = bias[n], bb1 = bias[n + 1];
#pragma unroll
            for (int h2 = 0; h2 < 2; h2++) {
                const size_t mm = m + h2 * 8;
                float v0 = c[h2 * 2 + 0] + bb0;
                float v1 = c[h2 * 2 + 1] + bb1;
                if (epi == 2) {
                    float2 xr = *(const float2*)&Xres[mm * 512 + n];
                    *(float2*)&outF[mm * 512 + n] = make_float2(
                        xr.x + fmaxf(v0, 0.f), xr.y + fmaxf(v1, 0.f));
                } else {
                    if (epi == 0)
                        *(float2*)&outF[mm * 512 + n] = make_float2(v0, v1);
                    *(unsigned*)&outB[mm * 512 + n] = pack2bf(v0, v1);
                }
            }
        }
}

__global__ __launch_bounds__(256) void gemm_s(
    const bf16* __restrict__ Qb, const bf16* __restrict__ Kb, bf16* __restrict__ S)
{
    __shared__ bf16 As[128 * SSTRIDE], Bs[128 * SSTRIDE];
    float acc[16][4];
#pragma unroll
    for (int i = 0; i < 16; i++)
#pragma unroll
        for (int j = 0; j < 4; j++) acc[i][j] = 0.f;

    const int q0 = blockIdx.x * 128, k0 = blockIdx.y * 128, bh = blockIdx.z;
    const int b = bh >> 3, h = bh & 7;
    mainloop<128>(Qb + ((size_t)(b * 1024 + q0)) * 512 + h * 64, 512,
                  Kb + ((size_t)(b * 1024 + k0)) * 512 + h * 64, 512, 64,
                  As, Bs, acc);

    const float scale = 0.04419417382415922f;
    const int tid = threadIdx.x, l = tid & 31, warp = tid >> 5;
    const int wm = warp & 3, wn = warp >> 2;
    bf16* out = S + (size_t)bh * 1024 * 1024;
#pragma unroll
    for (int mt = 0; mt < 2; mt++)
#pragma unroll
        for (int nt = 0; nt < 8; nt++) {
            const float* c = acc[mt * 8 + nt];
            const int q = q0 + wm * 32 + mt * 16 + (l >> 2);
            const int k = k0 + wn * 64 + nt * 8 + (l & 3) * 2;
#pragma unroll
            for (int h2 = 0; h2 < 2; h2++) {
                const size_t qq = q + h2 * 8;
                *(unsigned*)&out[qq * 1024 + k] =
                    pack2bf(c[h2 * 2 + 0] * scale, c[h2 * 2 + 1] * scale);
            }
        }
}

__global__ __launch_bounds__(256) void gemm_pv(
    const bf16* __restrict__ Pm, const bf16* __restrict__ Vt,
    const float* __restrict__ Qpf, float* __restrict__ Oh)
{
    __shared__ bf16 As[128 * SSTRIDE], Bs[64 * SSTRIDE];
    float acc[8][4];
#pragma unroll
    for (int i = 0; i < 8; i++)
#pragma unroll
        for (int j = 0; j < 4; j++) acc[i][j] = 0.f;

    const int q0 = blockIdx.x * 128, bh = blockIdx.y;
    const int b = bh >> 3, h = bh & 7;
    mainloop<64>(Pm + ((size_t)bh * 1024 + q0) * 1024, 1024,
                 Vt + (size_t)bh * 65536, 1024, 1024, As, Bs, acc);

    const int tid = threadIdx.x, l = tid & 31, warp = tid >> 5;
    const int wm = warp & 3, wn = warp >> 2;
#pragma unroll
    for (int mt = 0; mt < 2; mt++)
#pragma unroll
        for (int nt = 0; nt < 4; nt++) {
            const float* c = acc[mt * 4 + nt];
            const int q = q0 + wm * 32 + mt * 16 + (l >> 2);
            const int d = wn * 32 + nt * 8 + (l & 3) * 2;
#pragma unroll
            for (int h2 = 0; h2 < 2; h2++) {
                const size_t idx = ((size_t)(b * 1024) + q + h2 * 8) * 512 + h * 64 + d;
                float2 qp = *(const float2*)&Qpf[idx];
                *(float2*)&Oh[idx] = make_float2(qp.x + c[h2 * 2 + 0],
                                                 qp.y + c[h2 * 2 + 1]);
            }
        }
}

__global__ __launch_bounds__(128) void softmax_p(bf16* S)
{
    const size_t row = blockIdx.x;
    const int tid = threadIdx.x;
    __shared__ float red[8];
    const uint4 v = ((const uint4*)(S + row * 1024))[tid];
    float f[8];
    {
        unsigned u[4] = { v.x, v.y, v.z, v.w };
#pragma unroll
        for (int k = 0; k < 4; k++) {
            float2 ff = __bfloat1622float2(*reinterpret_cast<const __nv_bfloat162*>(&u[k]));
            f[2 * k] = ff.x; f[2 * k + 1] = ff.y;
        }
    }
    float mx = f[0];
#pragma unroll
    for (int k = 1; k < 8; k++) mx = fmaxf(mx, f[k]);
#pragma unroll
    for (int o = 16; o; o >>= 1) mx = fmaxf(mx, __shfl_xor_sync(~0u, mx, o));
    const int wid = tid >> 5, lane = tid & 31;
    if (lane == 0) red[wid] = mx;
    __syncthreads();
    mx = fmaxf(fmaxf(red[0], red[1]), fmaxf(red[2], red[3]));
    float e[8], s = 0.f;
#pragma unroll
    for (int k = 0; k < 8; k++) { e[k] = __expf(f[k] - mx); s += e[k]; }
#pragma unroll
    for (int o = 16; o; o >>= 1) s += __shfl_xor_sync(~0u, s, o);
    if (lane == 0) red[4 + wid] = s;
    __syncthreads();
    const float inv = 1.f / (red[4] + red[5] + red[6] + red[7]);
    uint4 o4;
    o4.x = pack2bf(e[0] * inv, e[1] * inv);
    o4.y = pack2bf(e[2] * inv, e[3] * inv);
    o4.z = pack2bf(e[4] * inv, e[5] * inv);
    o4.w = pack2bf(e[6] * inv, e[7] * inv);
    ((uint4*)(S + row * 1024))[tid] = o4;
}

__global__ void conv_split(const float* __restrict__ X, bf16* __restrict__ Hi,
                           bf16* __restrict__ Lo, int n4)
{
    int i = blockIdx.x * blockDim.x + threadIdx.x;
    if (i >= n4) return;
    float4 x = ((const float4*)X)[i];
    uint2 hp; hp.x = pack2bf(x.x, x.y); hp.y = pack2bf(x.z, x.w);
    ((uint2*)Hi)[i] = hp;
    if (Lo) {
        float h0 = __bfloat162float(__float2bfloat16_rn(x.x));
        float h1 = __bfloat162float(__float2bfloat16_rn(x.y));
        float h2 = __bfloat162float(__float2bfloat16_rn(x.z));
        float h3 = __bfloat162float(__float2bfloat16_rn(x.w));
        uint2 lp; lp.x = pack2bf(x.x - h0, x.y - h1); lp.y = pack2bf(x.z - h2, x.w - h3);
        ((uint2*)Lo)[i] = lp;
    }
}

__global__ void convT_w(const float* __restrict__ W, bf16* __restrict__ Thi,
                        bf16* __restrict__ Tlo)
{
    __shared__ float t[32][33];
    const int tx = threadIdx.x & 31, ty = threadIdx.x >> 5;
    const int k0 = blockIdx.y * 32, n0 = blockIdx.x * 32;
#pragma unroll
    for (int i = 0; i < 4; i++)
        t[ty + 8 * i][tx] = W[(size_t)(k0 + ty + 8 * i) * 512 + n0 + tx];
    __syncthreads();
#pragma unroll
    for (int i = 0; i < 4; i++) {
        int n = n0 + ty + 8 * i;
        float x = t[tx][ty + 8 * i];
        bf16 h = __float2bfloat16_rn(x);
        Thi[(size_t)n * 512 + k0 + tx] = h;
        if (Tlo) Tlo[(size_t)n * 512 + k0 + tx] = __float2bfloat16_rn(x - __bfloat162float(h));
    }
}

__global__ void transpose_v(const bf16* __restrict__ Vp, bf16* __restrict__ Vt)
{
    __shared__ unsigned short t[32][33];
    const int tx = threadIdx.x & 31, ty = threadIdx.x >> 5;
    const int t0 = blockIdx.x * 32, d0 = blockIdx.y * 32, bh = blockIdx.z;
    const int b = bh >> 3, h = bh & 7;
    const unsigned short* src = (const unsigned short*)Vp;
#pragma unroll
    for (int i = 0; i < 4; i++)
        t[ty + 8 * i][tx] = src[((size_t)(b * 1024 + t0 + ty + 8 * i)) * 512 + h * 64 + d0 + tx];
    __syncthreads();
    unsigned short* dst = (unsigned short*)Vt;
#pragma unroll
    for (int i = 0; i < 4; i++)
        dst[(size_t)bh * 65536 + (size_t)(d0 + ty + 8 * i) * 1024 + t0 + tx] = t[tx][ty + 8 * i];
}

__global__ __launch_bounds__(256) void ln512(
    const float* __restrict__ X, const float* __restrict__ g,
    const float* __restrict__ bb, float* __restrict__ Y,
    bf16* __restrict__ Hi, bf16* __restrict__ Lo)
{
    const size_t row = blockIdx.x;
    const int tid = threadIdx.x;
    const float* x = X + row * 512;
    const float v0 = x[tid], v1 = x[tid + 256];
    float s = v0 + v1, sq = v0 * v0 + v1 * v1;
    __shared__ float red[16];
#pragma unroll
    for (int off = 16; off; off >>= 1) {
        s  += __shfl_xor_sync(~0u, s,  off);
        sq += __shfl_xor_sync(~0u, sq, off);
    }
    const int wid = tid >> 5, lane = tid & 31;
    if (lane == 0) { red[wid * 2] = s; red[wid * 2 + 1] = sq; }
    __syncthreads();
    float sum = 0.f, sumsq = 0.f;
#pragma unroll
    for (int w = 0; w < 8; w++) { sum += red[w * 2]; sumsq += red[w * 2 + 1]; }
    const float mean = sum * (1.f / 512.f);
    const float var  = sumsq * (1.f / 512.f) - mean * mean;
    const float r    = rsqrtf(var + 1e-5f);
    const float y0 = (v0 - mean) * r * g[tid]       + bb[tid];
    const float y1 = (v1 - mean) * r * g[tid + 256] + bb[tid + 256];
    Y[row * 512 + tid]       = y0;
    Y[row * 512 + tid + 256] = y1;
    if (Hi) {
        bf16 h0 = __float2bfloat16_rn(y0), h1 = __float2bfloat16_rn(y1);
        Hi[row * 512 + tid]       = h0;
        Hi[row * 512 + tid + 256] = h1;
        Lo[row * 512 + tid]       = __float2bfloat16_rn(y0 - __bfloat162float(h0));
        Lo[row * 512 + tid + 256] = __float2bfloat16_rn(y1 - __bfloat162float(h1));
    }
}

extern "C" void kernel_launch(void* const* d_in, const int* in_sizes, int n_in,
                              void* d_out, int out_size)
{
    const float* Q  = (const float*)d_in[0];
    const float* K  = (const float*)d_in[1];
    const float* Wq = (const float*)d_in[2];
    const float* bq = (const float*)d_in[3];
    const float* Wk = (const float*)d_in[4];
    const float* bk = (const float*)d_in[5];
    const float* Wv = (const float*)d_in[6];
    const float* bv = (const float*)d_in[7];
    const float* Wo = (const float*)d_in[8];
    const float* bo = (const float*)d_in[9];
    const float* g0 = (const float*)d_in[10];
    const float* b0 = (const float*)d_in[11];
    const float* g1 = (const float*)d_in[12];
    const float* b1 = (const float*)d_in[13];
    float* out = (float*)d_out;

    bf16 *Qhi, *Qlo, *Khi, *Wqth, *Wqtl, *Wkt, *Wvt, *Woth, *Wotl;
    bf16 *Qpb, *Kpb, *Vpb, *Vt, *S, *X1hi, *X1lo;
    float *Qp, *Oh, *X1, *Y;
    cudaGetSymbolAddress((void**)&Qhi, g_Qhi);
    cudaGetSymbolAddress((void**)&Qlo, g_Qlo);
    cudaGetSymbolAddress((void**)&Khi, g_Khi);
    cudaGetSymbolAddress((void**)&Wqth, g_Wqt_hi);
    cudaGetSymbolAddress((void**)&Wqtl, g_Wqt_lo);
    cudaGetSymbolAddress((void**)&Wkt, g_Wkt);
    cudaGetSymbolAddress((void**)&Wvt, g_Wvt);
    cudaGetSymbolAddress((void**)&Woth, g_Wot_hi);
    cudaGetSymbolAddress((void**)&Wotl, g_Wot_lo);
    cudaGetSymbolAddress((void**)&Qp,  g_Qp);
    cudaGetSymbolAddress((void**)&Qpb, g_Qpb);
    cudaGetSymbolAddress((void**)&Kpb, g_Kpb);
    cudaGetSymbolAddress((void**)&Vpb, g_Vpb);
    cudaGetSymbolAddress((void**)&Vt,  g_Vt);
    cudaGetSymbolAddress((void**)&S,   g_S);
    cudaGetSymbolAddress((void**)&Oh,  g_Oh);
    cudaGetSymbolAddress((void**)&X1,  g_X1);
    cudaGetSymbolAddress((void**)&X1hi, g_X1hi);
    cudaGetSymbolAddress((void**)&X1lo, g_X1lo);
    cudaGetSymbolAddress((void**)&Y,   g_Y);

    const int n4 = MROWS * DV_ / 4;
    conv_split<<<(n4 + 255) / 256, 256>>>(Q, Qhi, Qlo, n4);
    conv_split<<<(n4 + 255) / 256, 256>>>(K, Khi, (bf16*)0, n4);
    dim3 wgrid(16, 16);
    convT_w<<<wgrid, 256>>>(Wq, Wqth, Wqtl);
    convT_w<<<wgrid, 256>>>(Wk, Wkt, (bf16*)0);
    convT_w<<<wgrid, 256>>>(Wv, Wvt, (bf16*)0);
    convT_w<<<wgrid, 256>>>(Wo, Woth, Wotl);

    dim3 pgrid(4, 64);
    gemm_proj<<<pgrid, 256>>>(Qhi, Qlo, Wqth, Wqtl, bq, (const float*)0, Qp, Qpb, 3, 0);
    gemm_proj<<<pgrid, 256>>>(Khi, (const bf16*)0, Wkt, (const bf16*)0, bk, (const float*)0, (float*)0, Kpb, 1, 1);
    gemm_proj<<<pgrid, 256>>>(Khi, (const bf16*)0, Wvt, (const bf16*)0, bv, (const float*)0, (float*)0, Vpb, 1, 1);

    transpose_v<<<dim3(32, 2, 64), 256>>>(Vpb, Vt);

    gemm_s<<<dim3(8, 8, 64), 256>>>(Qpb, Kpb, S);
    softmax_p<<<65536, 128>>>(S);
    gemm_pv<<<dim3(8, 64), 256>>>(S, Vt, Qp, Oh);

    ln512<<<MROWS, 256>>>(Oh, g0, b0, X1, X1hi, X1lo);
    gemm_proj<<<pgrid, 256>>>(X1hi, X1lo, Woth, Wotl, bo, X1, Y, (bf16*)0, 3, 2);
    ln512<<<MROWS, 256>>>(Y, g1, b1, out, (bf16*)0, (bf16*)0);
}

// round 7
// speedup vs baseline: 3.4240x; 1.2703x over previous
#include <cuda_runtime.h>
#include <cuda_bf16.h>
#include <math.h>

typedef __nv_bfloat16 bf16;

#define B_    8
#define NQ_   1024
#define DV_   512
#define MROWS (B_ * NQ_)
#define SSTRIDE 40

__device__ bf16  g_Qhi[MROWS * DV_];
__device__ bf16  g_Qlo[MROWS * DV_];
__device__ bf16  g_Khi[MROWS * DV_];
__device__ bf16  g_Wqt_hi[DV_ * DV_];
__device__ bf16  g_Wqt_lo[DV_ * DV_];
__device__ bf16  g_Wkt[DV_ * DV_];
__device__ bf16  g_Wvt[DV_ * DV_];
__device__ bf16  g_Wot_hi[DV_ * DV_];
__device__ bf16  g_Wot_lo[DV_ * DV_];
__device__ float g_Qp [MROWS * DV_];
__device__ bf16  g_Qpb[MROWS * DV_];
__device__ bf16  g_Kpb[MROWS * DV_];
__device__ bf16  g_Vpb[MROWS * DV_];
__device__ float g_Oh [MROWS * DV_];
__device__ float g_X1 [MROWS * DV_];
__device__ bf16  g_X1hi[MROWS * DV_];
__device__ bf16  g_X1lo[MROWS * DV_];
__device__ float g_Y  [MROWS * DV_];

__device__ __forceinline__ unsigned smem_u32(const void* p) {
    unsigned a;
    asm("{ .reg .u64 t; cvta.to.shared.u64 t, %1; cvt.u32.u64 %0, t; }" : "=r"(a) : "l"(p));
    return a;
}
__device__ __forceinline__ unsigned pack2bf(float a, float b) {
    __nv_bfloat162 t = __floats2bfloat162_rn(a, b);
    return *reinterpret_cast<unsigned*>(&t);
}

#define LDSM_X4(R0, R1, R2, R3, ADDR) \
    asm volatile("ldmatrix.sync.aligned.m8n8.x4.shared.b16 {%0,%1,%2,%3}, [%4];" \
                 : "=r"(R0), "=r"(R1), "=r"(R2), "=r"(R3) : "r"(ADDR))

#define LDSM_X4T(R0, R1, R2, R3, ADDR) \
    asm volatile("ldmatrix.sync.aligned.m8n8.x4.trans.shared.b16 {%0,%1,%2,%3}, [%4];" \
                 : "=r"(R0), "=r"(R1), "=r"(R2), "=r"(R3) : "r"(ADDR))

#define MMA16816(D, A, Bb) \
    asm volatile("mma.sync.aligned.m16n8k16.row.col.f32.bf16.bf16.f32 " \
                 "{%0,%1,%2,%3}, {%4,%5,%6,%7}, {%8,%9}, {%0,%1,%2,%3};" \
                 : "+f"((D)[0]), "+f"((D)[1]), "+f"((D)[2]), "+f"((D)[3]) \
                 : "r"((A)[0]), "r"((A)[1]), "r"((A)[2]), "r"((A)[3]), \
                   "r"((Bb)[0]), "r"((Bb)[1]))

// Block tile 128 x BN, 8 warps (4m x 2n), K chunks of 32.
template<int BN>
__device__ __forceinline__ void mainloop(
    const bf16* __restrict__ A, int lda,
    const bf16* __restrict__ B, int ldb, int K,
    bf16* As, bf16* Bs, float (*acc)[4])
{
    const int tid  = threadIdx.x;
    const int l    = tid & 31;
    const int warp = tid >> 5;
    const int wm   = warp & 3, wn = warp >> 2;
    const unsigned sAu = smem_u32(As), sBu = smem_u32(Bs);

    const int ar0 = tid >> 2,          ac0 = tid & 3;
    const int ar1 = (tid + 256) >> 2,  ac1 = tid & 3;
    const int br0 = tid >> 2,          bc0 = tid & 3;
    const int br1 = (tid + 256) >> 2,  bc1 = tid & 3;

    unsigned aAddr[2];
#pragma unroll
    for (int mt = 0; mt < 2; mt++)
        aAddr[mt] = sAu + (unsigned)(((wm * 32 + mt * 16 + (l & 15)) * SSTRIDE
                                      + (l >> 4) * 8) * 2);
    const int g = l >> 3, l8 = l & 7;
    unsigned bAddr[BN / 32];
#pragma unroll
    for (int j = 0; j < BN / 32; j++) {
        int row = wn * (BN / 2) + j * 16 + (g >> 1) * 8 + l8;
        bAddr[j] = sBu + (unsigned)((row * SSTRIDE + (g & 1) * 8) * 2);
    }

    uint4 pa0, pa1, pb0, pb1;
    pa0 = *(const uint4*)(A + (size_t)ar0 * lda + ac0 * 8);
    pa1 = *(const uint4*)(A + (size_t)ar1 * lda + ac1 * 8);
    pb0 = *(const uint4*)(B + (size_t)br0 * ldb + bc0 * 8);
    if (BN == 128) pb1 = *(const uint4*)(B + (size_t)br1 * ldb + bc1 * 8);

    const int nch = K >> 5;
    for (int kc = 0; kc < nch; kc++) {
        __syncthreads();
        *(uint4*)(As + ar0 * SSTRIDE + ac0 * 8) = pa0;
        *(uint4*)(As + ar1 * SSTRIDE + ac1 * 8) = pa1;
        *(uint4*)(Bs + br0 * SSTRIDE + bc0 * 8) = pb0;
        if (BN == 128) *(uint4*)(Bs + br1 * SSTRIDE + bc1 * 8) = pb1;
        __syncthreads();
        if (kc + 1 < nch) {
            const int ko = (kc + 1) * 32;
            pa0 = *(const uint4*)(A + (size_t)ar0 * lda + ko + ac0 * 8);
            pa1 = *(const uint4*)(A + (size_t)ar1 * lda + ko + ac1 * 8);
            pb0 = *(const uint4*)(B + (size_t)br0 * ldb + ko + bc0 * 8);
            if (BN == 128) pb1 = *(const uint4*)(B + (size_t)br1 * ldb + ko + bc1 * 8);
        }
#pragma unroll
        for (int s = 0; s < 2; s++) {
            unsigned af[2][4];
            LDSM_X4(af[0][0], af[0][1], af[0][2], af[0][3], aAddr[0] + s * 32);
            LDSM_X4(af[1][0], af[1][1], af[1][2], af[1][3], aAddr[1] + s * 32);
            unsigned bfm[BN / 16][2];
#pragma unroll
            for (int j = 0; j < BN / 32; j++)
                LDSM_X4(bfm[2 * j][0], bfm[2 * j][1],
                        bfm[2 * j + 1][0], bfm[2 * j + 1][1], bAddr[j] + s * 32);
#pragma unroll
            for (int mt = 0; mt < 2; mt++)
#pragma unroll
                for (int nt = 0; nt < BN / 16; nt++)
                    MMA16816(acc[mt * (BN / 16) + nt], af[mt], bfm[nt]);
        }
    }
}

// epi: 0 = bias -> f32 + bf16 ; 1 = bias -> bf16 ; 2 = Xres + relu -> f32
__global__ __launch_bounds__(256) void gemm_proj(
    const bf16* __restrict__ Ahi, const bf16* __restrict__ Alo,
    const bf16* __restrict__ Bhi, const bf16* __restrict__ Blo,
    const float* __restrict__ bias, const float* __restrict__ Xres,
    float* __restrict__ outF, bf16* __restrict__ outB, int npass, int epi)
{
    __shared__ bf16 As[128 * SSTRIDE], Bs[128 * SSTRIDE];
    float acc[16][4];
#pragma unroll
    for (int i = 0; i < 16; i++)
#pragma unroll
        for (int j = 0; j < 4; j++) acc[i][j] = 0.f;

    const int m0 = blockIdx.y * 128, n0 = blockIdx.x * 128;
    for (int p = 0; p < npass; p++) {
        const bf16* Ag = (p == 2) ? Alo : Ahi;
        const bf16* Bg = (p == 1) ? Blo : Bhi;
        mainloop<128>(Ag + (size_t)m0 * 512, 512, Bg + (size_t)n0 * 512, 512, 512,
                      As, Bs, acc);
    }

    const int tid = threadIdx.x, l = tid & 31, warp = tid >> 5;
    const int wm = warp & 3, wn = warp >> 2;
#pragma unroll
    for (int mt = 0; mt < 2; mt++)
#pragma unroll
        for (int nt = 0; nt < 8; nt++) {
            const float* c = acc[mt * 8 + nt];
            const int m = m0 + wm * 32 + mt * 16 + (l >> 2);
            const int n = n0 + wn * 64 + nt * 8 + (l & 3) * 2;
            const float bb0 = bias[n], bb1 = bias[n + 1];
#pragma unroll
            for (int h2 = 0; h2 < 2; h2++) {
                const size_t mm = m + h2 * 8;
                float v0 = c[h2 * 2 + 0] + bb0;
                float v1 = c[h2 * 2 + 1] + bb1;
                if (epi == 2) {
                    float2 xr = *(const float2*)&Xres[mm * 512 + n];
                    *(float2*)&outF[mm * 512 + n] = make_float2(
                        xr.x + fmaxf(v0, 0.f), xr.y + fmaxf(v1, 0.f));
                } else {
                    if (epi == 0)
                        *(float2*)&outF[mm * 512 + n] = make_float2(v0, v1);
                    *(unsigned*)&outB[mm * 512 + n] = pack2bf(v0, v1);
                }
            }
        }
}

// =================================================================
// Fused flash attention: one CTA per (qtile=128, bh). 8 warps, each
// warp owns 16 full query rows. O = Qp + softmax(Q K^T * scale) V.
// =================================================================
#define FS 72   // smem row stride (bf16) for 64-wide K/V tiles

__global__ __launch_bounds__(256) void flash_attn(
    const bf16* __restrict__ Qb, const bf16* __restrict__ Kb,
    const bf16* __restrict__ Vb, const float* __restrict__ Qpf,
    float* __restrict__ Oh)
{
    __shared__ bf16 Ksm[128 * FS];
    __shared__ bf16 Vsm[128 * FS];

    const int tid = threadIdx.x, l = tid & 31, w = tid >> 5;
    const int qt = blockIdx.x, bh = blockIdx.y;
    const int b = bh >> 3, h = bh & 7;
    const unsigned sK = smem_u32(Ksm), sV = smem_u32(Vsm);

    const bf16* Qg = Qb + ((size_t)(b * 1024 + qt * 128)) * 512 + h * 64;
    const bf16* Kg = Kb + ((size_t)(b * 1024)) * 512 + h * 64;
    const bf16* Vg = Vb + ((size_t)(b * 1024)) * 512 + h * 64;

    // stage Q tile through Ksm, load persistent A-fragments
#pragma unroll
    for (int i = 0; i < 4; i++) {
        int idx = tid + i * 256, r = idx >> 3, c8 = idx & 7;
        *(uint4*)(Ksm + r * FS + c8 * 8) = *(const uint4*)(Qg + (size_t)r * 512 + c8 * 8);
    }
    __syncthreads();
    unsigned qa[4][4];
    {
        const int row = w * 16 + (l & 15);
        const int colb = (l >> 4) * 8;
#pragma unroll
        for (int j = 0; j < 4; j++) {
            unsigned ad = sK + (unsigned)((row * FS + j * 16 + colb) * 2);
            LDSM_X4(qa[j][0], qa[j][1], qa[j][2], qa[j][3], ad);
        }
    }
    __syncthreads();

    float oacc[8][4];
#pragma unroll
    for (int i = 0; i < 8; i++)
#pragma unroll
        for (int j = 0; j < 4; j++) oacc[i][j] = 0.f;
    float m0 = -1e30f, m1 = -1e30f, l0 = 0.f, l1 = 0.f;
    const float scale = 0.04419417382415922f;  // 1/sqrt(512)

    const int g = l >> 3, l8 = l & 7;

    for (int kt = 0; kt < 8; kt++) {
        // copy K,V 128x64 tiles
#pragma unroll
        for (int i = 0; i < 4; i++) {
            int idx = tid + i * 256, r = idx >> 3, c8 = idx & 7;
            size_t go = (size_t)(kt * 128 + r) * 512 + c8 * 8;
            *(uint4*)(Ksm + r * FS + c8 * 8) = *(const uint4*)(Kg + go);
            *(uint4*)(Vsm + r * FS + c8 * 8) = *(const uint4*)(Vg + go);
        }
        __syncthreads();

        // S = Q K^T  (16 q-rows x 128 keys per warp)
        float sc[16][4];
#pragma unroll
        for (int i = 0; i < 16; i++)
#pragma unroll
            for (int j = 0; j < 4; j++) sc[i][j] = 0.f;
#pragma unroll
        for (int s = 0; s < 4; s++) {
#pragma unroll
            for (int t = 0; t < 8; t++) {
                unsigned r0, r1, r2, r3;
                unsigned ad = sK + (unsigned)(((t * 16 + (g >> 1) * 8 + l8) * FS
                                              + s * 16 + (g & 1) * 8) * 2);
                LDSM_X4(r0, r1, r2, r3, ad);
                unsigned bb0[2] = { r0, r1 }, bb1[2] = { r2, r3 };
                MMA16816(sc[2 * t],     qa[s], bb0);
                MMA16816(sc[2 * t + 1], qa[s], bb1);
            }
        }

        // online softmax (rows r0 = w*16 + l>>2, r1 = +8)
        float mx0 = -1e30f, mx1 = -1e30f;
#pragma unroll
        for (int t = 0; t < 16; t++) {
            sc[t][0] *= scale; sc[t][1] *= scale;
            sc[t][2] *= scale; sc[t][3] *= scale;
            mx0 = fmaxf(mx0, fmaxf(sc[t][0], sc[t][1]));
            mx1 = fmaxf(mx1, fmaxf(sc[t][2], sc[t][3]));
        }
        mx0 = fmaxf(mx0, __shfl_xor_sync(~0u, mx0, 1));
        mx0 = fmaxf(mx0, __shfl_xor_sync(~0u, mx0, 2));
        mx1 = fmaxf(mx1, __shfl_xor_sync(~0u, mx1, 1));
        mx1 = fmaxf(mx1, __shfl_xor_sync(~0u, mx1, 2));
        const float mn0 = fmaxf(m0, mx0), mn1 = fmaxf(m1, mx1);
        const float a0 = __expf(m0 - mn0), a1 = __expf(m1 - mn1);
        m0 = mn0; m1 = mn1;

        float sum0 = 0.f, sum1 = 0.f;
        unsigned pa[8][4];
#pragma unroll
        for (int t = 0; t < 8; t++) {
            float e00 = __expf(sc[2 * t][0] - mn0);
            float e01 = __expf(sc[2 * t][1] - mn0);
            float e10 = __expf(sc[2 * t][2] - mn1);
            float e11 = __expf(sc[2 * t][3] - mn1);
            float f00 = __expf(sc[2 * t + 1][0] - mn0);
            float f01 = __expf(sc[2 * t + 1][1] - mn0);
            float f10 = __expf(sc[2 * t + 1][2] - mn1);
            float f11 = __expf(sc[2 * t + 1][3] - mn1);
            sum0 += e00 + e01 + f00 + f01;
            sum1 += e10 + e11 + f10 + f11;
            pa[t][0] = pack2bf(e00, e01);
            pa[t][1] = pack2bf(e10, e11);
            pa[t][2] = pack2bf(f00, f01);
            pa[t][3] = pack2bf(f10, f11);
        }
        sum0 += __shfl_xor_sync(~0u, sum0, 1);
        sum0 += __shfl_xor_sync(~0u, sum0, 2);
        sum1 += __shfl_xor_sync(~0u, sum1, 1);
        sum1 += __shfl_xor_sync(~0u, sum1, 2);
        l0 = l0 * a0 + sum0;
        l1 = l1 * a1 + sum1;
#pragma unroll
        for (int d = 0; d < 8; d++) {
            oacc[d][0] *= a0; oacc[d][1] *= a0;
            oacc[d][2] *= a1; oacc[d][3] *= a1;
        }

        // O += P V  (V fragments via ldmatrix.trans on [t][d] tile)
#pragma unroll
        for (int s2 = 0; s2 < 8; s2++) {
#pragma unroll
            for (int gd = 0; gd < 4; gd++) {
                unsigned r0, r1, r2, r3;
                unsigned ad = sV + (unsigned)(((s2 * 16 + (g & 1) * 8 + l8) * FS
                                              + gd * 16 + (g >> 1) * 8) * 2);
                LDSM_X4T(r0, r1, r2, r3, ad);
                unsigned vb0[2] = { r0, r1 }, vb1[2] = { r2, r3 };
                MMA16816(oacc[2 * gd],     pa[s2], vb0);
                MMA16816(oacc[2 * gd + 1], pa[s2], vb1);
            }
        }
        __syncthreads();
    }

    // epilogue: normalize, add Qp residual, write
    const float inv0 = 1.f / l0, inv1 = 1.f / l1;
    const int r0 = w * 16 + (l >> 2), r1 = r0 + 8;
    const int cb = 2 * (l & 3);
    const size_t base0 = ((size_t)(b * 1024 + qt * 128 + r0)) * 512 + h * 64;
    const size_t base1 = ((size_t)(b * 1024 + qt * 128 + r1)) * 512 + h * 64;
#pragma unroll
    for (int t = 0; t < 8; t++) {
        const int d = t * 8 + cb;
        float2 q0 = *(const float2*)&Qpf[base0 + d];
        float2 q1 = *(const float2*)&Qpf[base1 + d];
        *(float2*)&Oh[base0 + d] = make_float2(q0.x + oacc[t][0] * inv0,
                                               q0.y + oacc[t][1] * inv0);
        *(float2*)&Oh[base1 + d] = make_float2(q1.x + oacc[t][2] * inv1,
                                               q1.y + oacc[t][3] * inv1);
    }
}

__global__ void conv_split(const float* __restrict__ X, bf16* __restrict__ Hi,
                           bf16* __restrict__ Lo, int n4)
{
    int i = blockIdx.x * blockDim.x + threadIdx.x;
    if (i >= n4) return;
    float4 x = ((const float4*)X)[i];
    uint2 hp; hp.x = pack2bf(x.x, x.y); hp.y = pack2bf(x.z, x.w);
    ((uint2*)Hi)[i] = hp;
    if (Lo) {
        float h0 = __bfloat162float(__float2bfloat16_rn(x.x));
        float h1 = __bfloat162float(__float2bfloat16_rn(x.y));
        float h2 = __bfloat162float(__float2bfloat16_rn(x.z));
        float h3 = __bfloat162float(__float2bfloat16_rn(x.w));
        uint2 lp; lp.x = pack2bf(x.x - h0, x.y - h1); lp.y = pack2bf(x.z - h2, x.w - h3);
        ((uint2*)Lo)[i] = lp;
    }
}

__global__ void convT_w(const float* __restrict__ W, bf16* __restrict__ Thi,
                        bf16* __restrict__ Tlo)
{
    __shared__ float t[32][33];
    const int tx = threadIdx.x & 31, ty = threadIdx.x >> 5;
    const int k0 = blockIdx.y * 32, n0 = blockIdx.x * 32;
#pragma unroll
    for (int i = 0; i < 4; i++)
        t[ty + 8 * i][tx] = W[(size_t)(k0 + ty + 8 * i) * 512 + n0 + tx];
    __syncthreads();
#pragma unroll
    for (int i = 0; i < 4; i++) {
        int n = n0 + ty + 8 * i;
        float x = t[tx][ty + 8 * i];
        bf16 h = __float2bfloat16_rn(x);
        Thi[(size_t)n * 512 + k0 + tx] = h;
        if (Tlo) Tlo[(size_t)n * 512 + k0 + tx] = __float2bfloat16_rn(x - __bfloat162float(h));
    }
}

__global__ __launch_bounds__(256) void ln512(
    const float* __restrict__ X, const float* __restrict__ g,
    const float* __restrict__ bb, float* __restrict__ Y,
    bf16* __restrict__ Hi, bf16* __restrict__ Lo)
{
    const size_t row = blockIdx.x;
    const int tid = threadIdx.x;
    const float* x = X + row * 512;
    const float v0 = x[tid], v1 = x[tid + 256];
    float s = v0 + v1, sq = v0 * v0 + v1 * v1;
    __shared__ float red[16];
#pragma unroll
    for (int off = 16; off; off >>= 1) {
        s  += __shfl_xor_sync(~0u, s,  off);
        sq += __shfl_xor_sync(~0u, sq, off);
    }
    const int wid = tid >> 5, lane = tid & 31;
    if (lane == 0) { red[wid * 2] = s; red[wid * 2 + 1] = sq; }
    __syncthreads();
    float sum = 0.f, sumsq = 0.f;
#pragma unroll
    for (int w = 0; w < 8; w++) { sum += red[w * 2]; sumsq += red[w * 2 + 1]; }
    const float mean = sum * (1.f / 512.f);
    const float var  = sumsq * (1.f / 512.f) - mean * mean;
    const float r    = rsqrtf(var + 1e-5f);
    const float y0 = (v0 - mean) * r * g[tid]       + bb[tid];
    const float y1 = (v1 - mean) * r * g[tid + 256] + bb[tid + 256];
    Y[row * 512 + tid]       = y0;
    Y[row * 512 + tid + 256] = y1;
    if (Hi) {
        bf16 h0 = __float2bfloat16_rn(y0), h1 = __float2bfloat16_rn(y1);
        Hi[row * 512 + tid]       = h0;
        Hi[row * 512 + tid + 256] = h1;
        Lo[row * 512 + tid]       = __float2bfloat16_rn(y0 - __bfloat162float(h0));
        Lo[row * 512 + tid + 256] = __float2bfloat16_rn(y1 - __bfloat162float(h1));
    }
}

extern "C" void kernel_launch(void* const* d_in, const int* in_sizes, int n_in,
                              void* d_out, int out_size)
{
    const float* Q  = (const float*)d_in[0];
    const float* K  = (const float*)d_in[1];
    const float* Wq = (const float*)d_in[2];
    const float* bq = (const float*)d_in[3];
    const float* Wk = (const float*)d_in[4];
    const float* bk = (const float*)d_in[5];
    const float* Wv = (const float*)d_in[6];
    const float* bv = (const float*)d_in[7];
    const float* Wo = (const float*)d_in[8];
    const float* bo = (const float*)d_in[9];
    const float* g0 = (const float*)d_in[10];
    const float* b0 = (const float*)d_in[11];
    const float* g1 = (const float*)d_in[12];
    const float* b1 = (const float*)d_in[13];
    float* out = (float*)d_out;

    bf16 *Qhi, *Qlo, *Khi, *Wqth, *Wqtl, *Wkt, *Wvt, *Woth, *Wotl;
    bf16 *Qpb, *Kpb, *Vpb, *X1hi, *X1lo;
    float *Qp, *Oh, *X1, *Y;
    cudaGetSymbolAddress((void**)&Qhi, g_Qhi);
    cudaGetSymbolAddress((void**)&Qlo, g_Qlo);
    cudaGetSymbolAddress((void**)&Khi, g_Khi);
    cudaGetSymbolAddress((void**)&Wqth, g_Wqt_hi);
    cudaGetSymbolAddress((void**)&Wqtl, g_Wqt_lo);
    cudaGetSymbolAddress((void**)&Wkt, g_Wkt);
    cudaGetSymbolAddress((void**)&Wvt, g_Wvt);
    cudaGetSymbolAddress((void**)&Woth, g_Wot_hi);
    cudaGetSymbolAddress((void**)&Wotl, g_Wot_lo);
    cudaGetSymbolAddress((void**)&Qp,  g_Qp);
    cudaGetSymbolAddress((void**)&Qpb, g_Qpb);
    cudaGetSymbolAddress((void**)&Kpb, g_Kpb);
    cudaGetSymbolAddress((void**)&Vpb, g_Vpb);
    cudaGetSymbolAddress((void**)&Oh,  g_Oh);
    cudaGetSymbolAddress((void**)&X1,  g_X1);
    cudaGetSymbolAddress((void**)&X1hi, g_X1hi);
    cudaGetSymbolAddress((void**)&X1lo, g_X1lo);
    cudaGetSymbolAddress((void**)&Y,   g_Y);

    const int n4 = MROWS * DV_ / 4;
    conv_split<<<(n4 + 255) / 256, 256>>>(Q, Qhi, Qlo, n4);
    conv_split<<<(n4 + 255) / 256, 256>>>(K, Khi, (bf16*)0, n4);
    dim3 wgrid(16, 16);
    convT_w<<<wgrid, 256>>>(Wq, Wqth, Wqtl);
    convT_w<<<wgrid, 256>>>(Wk, Wkt, (bf16*)0);
    convT_w<<<wgrid, 256>>>(Wv, Wvt, (bf16*)0);
    convT_w<<<wgrid, 256>>>(Wo, Woth, Wotl);

    dim3 pgrid(4, 64);
    gemm_proj<<<pgrid, 256>>>(Qhi, Qlo, Wqth, Wqtl, bq, (const float*)0, Qp, Qpb, 3, 0);
    gemm_proj<<<pgrid, 256>>>(Khi, (const bf16*)0, Wkt, (const bf16*)0, bk, (const float*)0, (float*)0, Kpb, 1, 1);
    gemm_proj<<<pgrid, 256>>>(Khi, (const bf16*)0, Wvt, (const bf16*)0, bv, (const float*)0, (float*)0, Vpb, 1, 1);

    flash_attn<<<dim3(8, 64), 256>>>(Qpb, Kpb, Vpb, Qp, Oh);

    ln512<<<MROWS, 256>>>(Oh, g0, b0, X1, X1hi, X1lo);
    gemm_proj<<<pgrid, 256>>>(X1hi, X1lo, Woth, Wotl, bo, X1, Y, (bf16*)0, 3, 2);
    ln512<<<MROWS, 256>>>(Y, g1, b1, out, (bf16*)0, (bf16*)0);
}